// round 1
// baseline (speedup 1.0000x reference)
#include <cuda_runtime.h>

#define NB   2
#define NS   1024
#define ND   1024
#define NH   16
#define NHD  64
#define NNC  64     // number of compression blocks
#define NCB  16     // compression block size
#define NSB  8
#define NJ   2
#define NWIN 256

#define INVS 0.125f       // 1/sqrt(64)
#define NEG  (-1e30f)

// ---------------- scratch (device globals; no allocation allowed) ----------------
__device__ float g_q [NB*NS*ND];
__device__ float g_k [NB*NS*ND];
__device__ float g_v [NB*NS*ND];
__device__ float g_ck[NB*NNC*ND];
__device__ float g_cv[NB*NNC*ND];
__device__ float g_oc[NB*NS*ND];   // compressed-branch output
__device__ float g_os[NB*NS*ND];   // selected-branch output
__device__ float g_ow[NB*NS*ND];   // window-branch output
__device__ float g_pre[NB*NS*ND];  // gated sum (input of final GEMM)
__device__ int   g_top[NB*NS*NJ];  // top-2 block indices

// ---------------- GEMM: C[M,N] = A[M,K] @ B[K,N]  (+pe / +bias epilogue) ----------
// BM=128, BN=64, BK=16, 256 threads, 8x4 per thread.
// mode 0: plain  | mode 1: += wpe[(m%16)*1024 + n]  | mode 2: += bias[n]
__global__ __launch_bounds__(256) void sgemm_kernel(
    const float* __restrict__ A, const float* __restrict__ Bm,
    float* __restrict__ C, int M, int N, int K,
    int mode, const float* __restrict__ extra)
{
    __shared__ float As[16][132];   // transposed A tile, padded
    __shared__ float Bs[16][64];

    const int tid = threadIdx.x;
    const int bm  = blockIdx.y * 128;
    const int bn  = blockIdx.x * 64;
    const int tx  = tid & 15;      // col group (4 cols)
    const int ty  = tid >> 4;      // row group (8 rows)

    const int arow = tid >> 1;         // 0..127
    const int acol = (tid & 1) * 8;    // 0 or 8
    const int brow = tid >> 4;         // 0..15
    const int bcol = (tid & 15) * 4;

    float acc[8][4];
#pragma unroll
    for (int i = 0; i < 8; i++)
#pragma unroll
        for (int j = 0; j < 4; j++) acc[i][j] = 0.f;

    for (int k0 = 0; k0 < K; k0 += 16) {
        float4 a0 = *(const float4*)(A + (bm + arow) * K + k0 + acol);
        float4 a1 = *(const float4*)(A + (bm + arow) * K + k0 + acol + 4);
        As[acol+0][arow] = a0.x; As[acol+1][arow] = a0.y;
        As[acol+2][arow] = a0.z; As[acol+3][arow] = a0.w;
        As[acol+4][arow] = a1.x; As[acol+5][arow] = a1.y;
        As[acol+6][arow] = a1.z; As[acol+7][arow] = a1.w;
        float4 b4 = *(const float4*)(Bm + (k0 + brow) * N + bn + bcol);
        *(float4*)&Bs[brow][bcol] = b4;
        __syncthreads();

#pragma unroll
        for (int kk = 0; kk < 16; kk++) {
            float4 t0 = *(const float4*)&As[kk][ty * 8];
            float4 t1 = *(const float4*)&As[kk][ty * 8 + 4];
            float4 bb = *(const float4*)&Bs[kk][tx * 4];
            float ar[8] = {t0.x, t0.y, t0.z, t0.w, t1.x, t1.y, t1.z, t1.w};
            float br[4] = {bb.x, bb.y, bb.z, bb.w};
#pragma unroll
            for (int i = 0; i < 8; i++)
#pragma unroll
                for (int j = 0; j < 4; j++) acc[i][j] += ar[i] * br[j];
        }
        __syncthreads();
    }

#pragma unroll
    for (int i = 0; i < 8; i++) {
        int m = bm + ty * 8 + i;
#pragma unroll
        for (int j = 0; j < 4; j++) {
            int n = bn + tx * 4 + j;
            float vv = acc[i][j];
            if (mode == 1)      vv += extra[(m & 15) * 1024 + n];
            else if (mode == 2) vv += extra[n];
            C[m * N + n] = vv;
        }
    }
}

// ---------------- compression: ck/cv[b,n,d] = sum_t w[t] * k/v[b, n*16+t, d] ------
__global__ __launch_bounds__(256) void compress_kernel(
    const float* __restrict__ wkc, const float* __restrict__ wvc)
{
    int idx = blockIdx.x * blockDim.x + threadIdx.x;   // 131072 total
    int d = idx & 1023;
    int n = (idx >> 10) & 63;
    int b = idx >> 16;
    const float* kb = g_k + (b * NS + n * NCB) * ND + d;
    const float* vb = g_v + (b * NS + n * NCB) * ND + d;
    float sk = 0.f, sv = 0.f;
#pragma unroll
    for (int t = 0; t < NCB; t++) {
        sk += wkc[t] * kb[t * ND];
        sv += wvc[t] * vb[t * ND];
    }
    g_ck[idx] = sk;
    g_cv[idx] = sv;
}

// ---------------- compressed attention + imp + top-2 ------------------------------
// block = (b,s), 512 threads, warp h handles head h.
__global__ __launch_bounds__(512) void comp_attn_kernel()
{
    const int bs = blockIdx.x;
    const int b  = bs >> 10;
    const int tid = threadIdx.x;
    const int h = tid >> 5, lane = tid & 31;

    __shared__ float sc_s[16][64];
    __shared__ float imp_s[64];

    const float2 q2 = *(const float2*)(g_q + bs * ND + h * 64 + lane * 2);

    float s0 = 0.f, s1 = 0.f;
    for (int n = 0; n < 64; n++) {
        float2 c2 = *(const float2*)(g_ck + (b * 64 + n) * ND + h * 64 + lane * 2);
        float p = q2.x * c2.x + q2.y * c2.y;
#pragma unroll
        for (int off = 16; off > 0; off >>= 1)
            p += __shfl_xor_sync(0xffffffffu, p, off);
        p *= INVS;
        if (lane == (n & 31)) { if (n < 32) s0 = p; else s1 = p; }
        if (lane == 0) sc_s[h][n] = p;
    }
    // softmax over 64 compressed blocks (lane holds n=lane, n=lane+32)
    float mx = fmaxf(s0, s1);
#pragma unroll
    for (int off = 16; off > 0; off >>= 1)
        mx = fmaxf(mx, __shfl_xor_sync(0xffffffffu, mx, off));
    float p0 = __expf(s0 - mx), p1 = __expf(s1 - mx);
    float sum = p0 + p1;
#pragma unroll
    for (int off = 16; off > 0; off >>= 1)
        sum += __shfl_xor_sync(0xffffffffu, sum, off);
    float rs = 1.f / sum;

    float2 acc = make_float2(0.f, 0.f);
    for (int n = 0; n < 64; n++) {
        float pn = __shfl_sync(0xffffffffu, n < 32 ? p0 : p1, n & 31);
        float2 v2 = *(const float2*)(g_cv + (b * 64 + n) * ND + h * 64 + lane * 2);
        acc.x += pn * v2.x; acc.y += pn * v2.y;
    }
    acc.x *= rs; acc.y *= rs;
    *(float2*)(g_oc + bs * ND + h * 64 + lane * 2) = acc;

    __syncthreads();
    if (tid < 64) {
        float v = 0.f;
#pragma unroll
        for (int hh = 0; hh < 16; hh++) v += sc_s[hh][tid];
        imp_s[tid] = v;
    }
    __syncthreads();
    if (tid < 32) {
        float v0 = imp_s[tid], v1 = imp_s[tid + 32];
        float bv; int bi;
        if (v0 >= v1) { bv = v0; bi = tid; } else { bv = v1; bi = tid + 32; }
#pragma unroll
        for (int off = 16; off > 0; off >>= 1) {
            float ov = __shfl_xor_sync(0xffffffffu, bv, off);
            int   oi = __shfl_xor_sync(0xffffffffu, bi, off);
            if (ov > bv || (ov == bv && oi < bi)) { bv = ov; bi = oi; }
        }
        int top1 = bi;
        float w0 = (tid == top1)      ? NEG : v0;
        float w1 = (tid + 32 == top1) ? NEG : v1;
        float bv2; int bi2;
        if (w0 >= w1) { bv2 = w0; bi2 = tid; } else { bv2 = w1; bi2 = tid + 32; }
#pragma unroll
        for (int off = 16; off > 0; off >>= 1) {
            float ov = __shfl_xor_sync(0xffffffffu, bv2, off);
            int   oi = __shfl_xor_sync(0xffffffffu, bi2, off);
            if (ov > bv2 || (ov == bv2 && oi < bi2)) { bv2 = ov; bi2 = oi; }
        }
        if (tid == 0) { g_top[bs * 2] = top1; g_top[bs * 2 + 1] = bi2; }
    }
}

// ---------------- selected attention (cross-batch gather per reference) -----------
// For B=J=2: blk[b,s,j] = top_idx[j, s, b], keys/values come from batch j.
__global__ __launch_bounds__(512) void sel_attn_kernel()
{
    const int bs = blockIdx.x;
    const int b  = bs >> 10, s = bs & 1023;
    const int tid = threadIdx.x;
    const int h = tid >> 5, lane = tid & 31;

    __shared__ int blk_s[2];
    if (tid < 2) blk_s[tid] = g_top[(tid * NS + s) * 2 + b];
    __syncthreads();

    const float2 q2 = *(const float2*)(g_q + bs * ND + h * 64 + lane * 2);

    float myscore = NEG;
#pragma unroll
    for (int m = 0; m < 16; m++) {
        int j = m >> 3, t = m & 7;
        int tok = blk_s[j] * NCB + t;
        float2 k2 = *(const float2*)(g_k + (j * NS + tok) * ND + h * 64 + lane * 2);
        float p = q2.x * k2.x + q2.y * k2.y;
#pragma unroll
        for (int off = 16; off > 0; off >>= 1)
            p += __shfl_xor_sync(0xffffffffu, p, off);
        p *= INVS;
        if (lane == m) myscore = p;
    }
    float mx = myscore;
#pragma unroll
    for (int off = 16; off > 0; off >>= 1)
        mx = fmaxf(mx, __shfl_xor_sync(0xffffffffu, mx, off));
    float p = __expf(myscore - mx);          // lanes >= 16 -> 0
    float sum = p;
#pragma unroll
    for (int off = 16; off > 0; off >>= 1)
        sum += __shfl_xor_sync(0xffffffffu, sum, off);
    float rs = 1.f / sum;

    float2 acc = make_float2(0.f, 0.f);
#pragma unroll
    for (int m = 0; m < 16; m++) {
        float pm = __shfl_sync(0xffffffffu, p, m);
        int j = m >> 3, t = m & 7;
        int tok = blk_s[j] * NCB + t;
        float2 v2 = *(const float2*)(g_v + (j * NS + tok) * ND + h * 64 + lane * 2);
        acc.x += pm * v2.x; acc.y += pm * v2.y;
    }
    acc.x *= rs; acc.y *= rs;
    *(float2*)(g_os + bs * ND + h * 64 + lane * 2) = acc;
}

// ---------------- sliding-window attention (flash-style, 64q x 64k tiles) ---------
// grid (qt=16, h=16, b=2), 512 threads (16 warps, 4 q-rows each).
__global__ __launch_bounds__(512) void win_attn_kernel()
{
    const int qt = blockIdx.x, h = blockIdx.y, b = blockIdx.z;
    const int tid = threadIdx.x;
    const int w = tid >> 5, lane = tid & 31;

    __shared__ float q_s[64 * 64];
    __shared__ float kT [64 * 64];   // [d][c], XOR-swizzled (c ^ (d&31))
    __shared__ float v_s[64 * 64];   // [c][d]

    const int qbase = qt * 64;

    for (int i = tid; i < 4096; i += 512) {
        int r = i >> 6, d = i & 63;
        q_s[i] = g_q[(b * NS + qbase + r) * ND + h * 64 + d];
    }

    float2 acc[4];
    float mrow[4], lrow[4];
#pragma unroll
    for (int i = 0; i < 4; i++) {
        acc[i] = make_float2(0.f, 0.f);
        mrow[i] = NEG; lrow[i] = 0.f;
    }

    const int kt_lo = (qt >= 4) ? qt - 4 : 0;
    for (int kt = kt_lo; kt <= qt; kt++) {
        const int kbase = kt * 64;
        __syncthreads();
        for (int i = tid; i < 4096; i += 512) {
            int c = i >> 6, d = i & 63;
            const int g = (b * NS + kbase + c) * ND + h * 64 + d;
            kT [d * 64 + (c ^ (d & 31))] = g_k[g];
            v_s[i] = g_v[g];
        }
        __syncthreads();

#pragma unroll
        for (int i = 0; i < 4; i++) {
            const int r  = w * 4 + i;
            const int qi = qbase + r;
            const float* qrow = q_s + r * 64;
            float sc0 = 0.f, sc1 = 0.f;
#pragma unroll 16
            for (int d = 0; d < 64; d++) {
                float qv = qrow[d];
                sc0 += qv * kT[d * 64 + ( lane       ^ (d & 31))];
                sc1 += qv * kT[d * 64 + ((lane + 32) ^ (d & 31))];
            }
            const int j0 = kbase + lane, j1 = kbase + lane + 32;
            sc0 = (j0 <= qi && qi - j0 <= NWIN) ? sc0 * INVS : NEG;
            sc1 = (j1 <= qi && qi - j1 <= NWIN) ? sc1 * INVS : NEG;

            float mnew = fmaxf(sc0, sc1);
#pragma unroll
            for (int off = 16; off > 0; off >>= 1)
                mnew = fmaxf(mnew, __shfl_xor_sync(0xffffffffu, mnew, off));
            mnew = fmaxf(mnew, mrow[i]);
            float scale = __expf(mrow[i] - mnew);
            float p0 = __expf(sc0 - mnew), p1 = __expf(sc1 - mnew);
            float ps = p0 + p1;
#pragma unroll
            for (int off = 16; off > 0; off >>= 1)
                ps += __shfl_xor_sync(0xffffffffu, ps, off);
            lrow[i] = lrow[i] * scale + ps;
            mrow[i] = mnew;

            float ax = acc[i].x * scale, ay = acc[i].y * scale;
#pragma unroll 16
            for (int c = 0; c < 64; c++) {
                float pc = __shfl_sync(0xffffffffu, c < 32 ? p0 : p1, c & 31);
                float2 v2 = *(const float2*)&v_s[c * 64 + lane * 2];
                ax += pc * v2.x; ay += pc * v2.y;
            }
            acc[i].x = ax; acc[i].y = ay;
        }
    }

#pragma unroll
    for (int i = 0; i < 4; i++) {
        const int r = w * 4 + i;
        const float rl = 1.f / lrow[i];
        float2 o = make_float2(acc[i].x * rl, acc[i].y * rl);
        *(float2*)(g_ow + (b * NS + qbase + r) * ND + h * 64 + lane * 2) = o;
    }
}

// ---------------- gates + branch combination --------------------------------------
__global__ __launch_bounds__(256) void gate_combine_kernel(
    const float* __restrict__ x, const float* __restrict__ Wg,
    const float* __restrict__ bg)
{
    const int bs = blockIdx.x;
    const int tid = threadIdx.x;
    __shared__ float red[3][256];
    __shared__ float gsh[3];

    const float* xr = x + bs * ND;
    float a0 = 0.f, a1 = 0.f, a2 = 0.f;
    for (int d = tid; d < ND; d += 256) {
        float xv = xr[d];
        a0 += xv * Wg[d * 3 + 0];
        a1 += xv * Wg[d * 3 + 1];
        a2 += xv * Wg[d * 3 + 2];
    }
    red[0][tid] = a0; red[1][tid] = a1; red[2][tid] = a2;
    __syncthreads();
    for (int sft = 128; sft > 0; sft >>= 1) {
        if (tid < sft) {
            red[0][tid] += red[0][tid + sft];
            red[1][tid] += red[1][tid + sft];
            red[2][tid] += red[2][tid + sft];
        }
        __syncthreads();
    }
    if (tid < 3) gsh[tid] = 1.f / (1.f + __expf(-(red[tid][0] + bg[tid])));
    __syncthreads();
    const float g0 = gsh[0], g1 = gsh[1], g2 = gsh[2];
    const int base = bs * ND;
    for (int d = tid; d < ND; d += 256)
        g_pre[base + d] = g0 * g_oc[base + d] + g1 * g_os[base + d] + g2 * g_ow[base + d];
}

// ---------------- launcher ---------------------------------------------------------
extern "C" void kernel_launch(void* const* d_in, const int* in_sizes, int n_in,
                              void* d_out, int out_size)
{
    (void)in_sizes; (void)n_in; (void)out_size;
    const float* x   = (const float*)d_in[0];
    const float* Wq  = (const float*)d_in[1];
    const float* Wk  = (const float*)d_in[2];
    const float* Wv  = (const float*)d_in[3];
    const float* Wo  = (const float*)d_in[4];
    const float* bo  = (const float*)d_in[5];
    const float* Wg  = (const float*)d_in[6];
    const float* bg  = (const float*)d_in[7];
    const float* wkc = (const float*)d_in[8];
    const float* wvc = (const float*)d_in[9];
    const float* wpe = (const float*)d_in[10];
    float* out = (float*)d_out;

    void *pq, *pk, *pv, *ppre;
    cudaGetSymbolAddress(&pq,   g_q);
    cudaGetSymbolAddress(&pk,   g_k);
    cudaGetSymbolAddress(&pv,   g_v);
    cudaGetSymbolAddress(&ppre, g_pre);

    const int M = NB * NS;                 // 2048
    dim3 gemm_grid(ND / 64, M / 128);      // (16,16)

    // q/k/v projections (pe fused into k/v epilogue)
    sgemm_kernel<<<gemm_grid, 256>>>(x, Wq, (float*)pq, M, ND, ND, 0, nullptr);
    sgemm_kernel<<<gemm_grid, 256>>>(x, Wk, (float*)pk, M, ND, ND, 1, wpe);
    sgemm_kernel<<<gemm_grid, 256>>>(x, Wv, (float*)pv, M, ND, ND, 1, wpe);

    // block compression
    compress_kernel<<<(NB * NNC * ND) / 256, 256>>>(wkc, wvc);

    // compressed attention + importance + top-2 (must complete for both batches
    // before the selected branch, which gathers cross-batch)
    comp_attn_kernel<<<NB * NS, 512>>>();

    // selected + window branches
    sel_attn_kernel<<<NB * NS, 512>>>();
    win_attn_kernel<<<dim3(NS / 64, NH, NB), 512>>>();

    // gates + combine, then output projection
    gate_combine_kernel<<<NB * NS, 256>>>(x, Wg, bg);
    sgemm_kernel<<<gemm_grid, 256>>>((const float*)ppre, Wo, out, M, ND, ND, 2, bo);
}